// round 2
// baseline (speedup 1.0000x reference)
#include <cuda_runtime.h>

// Problem constants
#define CODE 2048
#define ARR  512
#define LENS 16384
#define NANG 181

// GEMM1 tiling: block tile 256(a) x 32(n), BK=16, thread tile 8(a) x 4(n), 256 threads
#define KSPLIT 64
#define KCHUNK (LENS / KSPLIT)   // 256
#define BM 256
#define BN 32
#define BK 16
#define NTILES ((NANG + BN - 1) / BN)   // 6
#define ATILES (ARR / BM)               // 2

// Codes per block in sweep kernel
#define CPB 8
#define SWEEP_BLOCKS (CODE / CPB)   // 256

// ---------------- device scratch (no allocations allowed) ----------------
__device__ float g_Bp[KSPLIT][2][ARR * NANG];   // split-K partials (re, im), ~47 MB
__device__ float g_Bre[ARR * NANG];
__device__ float g_Bim[ARR * NANG];
__device__ float g_P[SWEEP_BLOCKS];
__device__ float g_D[SWEEP_BLOCKS];

typedef unsigned long long u64;

// ---------------- packed f32x2 helpers (ptxas won't auto-fuse; PTX only) ----------------
__device__ __forceinline__ u64 pk2(float lo, float hi) {
    u64 r;
    asm("mov.b64 %0, {%1, %2};" : "=l"(r) : "f"(lo), "f"(hi));
    return r;
}
__device__ __forceinline__ u64 ffma2(u64 a, u64 b, u64 c) {
    u64 d;
    asm("fma.rn.f32x2 %0, %1, %2, %3;" : "=l"(d) : "l"(a), "l"(b), "l"(c));
    return d;
}
__device__ __forceinline__ float2 unpk2(u64 v) {
    float lo, hi;
    asm("mov.b64 {%0, %1}, %2;" : "=f"(lo), "=f"(hi) : "l"(v));
    return make_float2(lo, hi);
}

// ---------------- GEMM1: B = (G * theta_n) @ steer, complex, split-K ----------------
// Grid: (NTILES=6, ATILES=2, KSPLIT=64) = 768 blocks, 256 threads.
// Thread grid 8(n) x 32(a); each thread owns an 8(a) x 4(n) complex micro-tile.
__global__ __launch_bounds__(256) void gemm1_kernel(
    const float* __restrict__ theta_re, const float* __restrict__ theta_im,
    const float* __restrict__ G_re,     const float* __restrict__ G_im,
    const float* __restrict__ steer_re, const float* __restrict__ steer_im)
{
    __shared__ float sAre[BK][BM + 1];   // stride 257: conflict-free STS/LDS
    __shared__ float sAim[BK][BM + 1];
    __shared__ float sBre[BK][BN];
    __shared__ float sBim[BK][BN];

    const int tid   = threadIdx.x;
    const int n0    = blockIdx.x * BN;
    const int a0    = blockIdx.y * BM;
    const int kbase = blockIdx.z * KCHUNK;

    const int nt = tid & 7;          // n-thread: 8 x Tn=4 -> 32 n
    const int at = tid >> 3;         // a-thread: 32 x Ta=8 -> 256 a
    const int ca = at * 8;
    const int cn = nt * 4;

    // A-loader: lt = tid&15 (k within tile), chunk = tid>>4 (16 a-groups of 16)
    const int lt = tid & 15;
    const int chA = tid >> 4;
    // B-loader: n = tid&31 contiguous, l = tid>>5 + 8*i
    const int nB = tid & 31;
    const int lB = tid >> 5;
    const int gnB = n0 + nB;
    const bool nBok = (gnB < NANG);

    u64 acc[8][4];
#pragma unroll
    for (int i = 0; i < 8; ++i)
#pragma unroll
        for (int j = 0; j < 4; ++j) acc[i][j] = pk2(0.f, 0.f);

    for (int kt = 0; kt < KCHUNK / BK; ++kt) {
        const int kb = kbase + kt * BK;
        __syncthreads();   // previous compute done before overwriting tiles

        // normalized theta for this thread's k-slot
        float tr = theta_re[kb + lt];
        float ti = theta_im[kb + lt];
        const float rn = rsqrtf(tr * tr + ti * ti);
        tr *= rn; ti *= rn;

        // A tile: (G * theta), 16 a-rows per thread
#pragma unroll
        for (int i = 0; i < 16; ++i) {
            const int a = chA * 16 + i;
            const float gr = G_re[(size_t)(a0 + a) * LENS + kb + lt];
            const float gi = G_im[(size_t)(a0 + a) * LENS + kb + lt];
            sAre[lt][a] = gr * tr - gi * ti;
            sAim[lt][a] = gr * ti + gi * tr;
        }
        // B tile: steer, 2 l-rows per thread (zero-padded beyond NANG)
#pragma unroll
        for (int i = 0; i < 2; ++i) {
            const int l = lB + 8 * i;
            float sr = 0.f, si = 0.f;
            if (nBok) {
                sr = steer_re[(size_t)(kb + l) * NANG + gnB];
                si = steer_im[(size_t)(kb + l) * NANG + gnB];
            }
            sBre[l][nB] = sr;
            sBim[l][nB] = si;
        }
        __syncthreads();

#pragma unroll
        for (int k = 0; k < BK; ++k) {
            u64 bp[4], bq[4];
#pragma unroll
            for (int j = 0; j < 4; ++j) {
                const float br = sBre[k][cn + j];
                const float bi = sBim[k][cn + j];
                bp[j] = pk2(br, bi);
                bq[j] = pk2(-bi, br);
            }
#pragma unroll
            for (int i = 0; i < 8; ++i) {
                const float ar = sAre[k][ca + i];
                const float ai = sAim[k][ca + i];
                const u64 ap = pk2(ar, ar);
                const u64 aq = pk2(ai, ai);
#pragma unroll
                for (int j = 0; j < 4; ++j)
                    acc[i][j] = ffma2(ap, bp[j], ffma2(aq, bq[j], acc[i][j]));
            }
        }
    }

    // store partials (disjoint per blockIdx.z -> deterministic, no atomics)
    float* __restrict__ outre = g_Bp[blockIdx.z][0];
    float* __restrict__ outim = g_Bp[blockIdx.z][1];
#pragma unroll
    for (int i = 0; i < 8; ++i) {
#pragma unroll
        for (int j = 0; j < 4; ++j) {
            const int gn = n0 + cn + j;
            if (gn < NANG) {
                const float2 v = unpk2(acc[i][j]);
                outre[(a0 + ca + i) * NANG + gn] = v.x;
                outim[(a0 + ca + i) * NANG + gn] = v.y;
            }
        }
    }
}

// ---------------- reduce split-K partials into B ----------------
__global__ __launch_bounds__(256) void reduceB_kernel()
{
    const int i = blockIdx.x * blockDim.x + threadIdx.x;
    if (i < ARR * NANG) {
        float sr = 0.f, si = 0.f;
#pragma unroll 8
        for (int s = 0; s < KSPLIT; ++s) {
            sr += g_Bp[s][0][i];
            si += g_Bp[s][1][i];
        }
        g_Bre[i] = sr;
        g_Bim[i] = si;
    }
}

// ---------------- sweep: sout = w_n @ B fused with |.|^2 reduction + diag gather ----------------
// Grid: CODE/CPB = 256 blocks, 192 threads (thread n < 181 owns one angle).
__global__ __launch_bounds__(192) void sweep_kernel(
    const float* __restrict__ w_re, const float* __restrict__ w_im,
    const int* __restrict__ sweep_angle)
{
    __shared__ float2 sw[CPB][ARR];   // normalized w rows for this block's codes (32 KB)
    __shared__ float redP[6], redD[6];

    const int tid = threadIdx.x;
    const int c0  = blockIdx.x * CPB;

    for (int idx = tid; idx < CPB * ARR; idx += 192) {
        const int c = idx >> 9;       // / ARR
        const int a = idx & (ARR - 1);
        const float wr = w_re[(size_t)(c0 + c) * ARR + a];
        const float wi = w_im[(size_t)(c0 + c) * ARR + a];
        const float rn = rsqrtf(wr * wr + wi * wi);
        sw[c][a] = make_float2(wr * rn, wi * rn);
    }
    __syncthreads();

    float sumP = 0.f, sumD = 0.f;
    const int n = tid;
    if (n < NANG) {
        u64 acc[CPB];
#pragma unroll
        for (int c = 0; c < CPB; ++c) acc[c] = pk2(0.f, 0.f);

#pragma unroll 4
        for (int a = 0; a < ARR; ++a) {
            const float br = g_Bre[a * NANG + n];   // coalesced across threads; B is L2-resident
            const float bi = g_Bim[a * NANG + n];
            const u64 bp = pk2(br, bi);
            const u64 bq = pk2(-bi, br);
#pragma unroll
            for (int c = 0; c < CPB; ++c) {
                const float2 w = sw[c][a];          // broadcast LDS.64
                acc[c] = ffma2(pk2(w.x, w.x), bp, ffma2(pk2(w.y, w.y), bq, acc[c]));
            }
        }
#pragma unroll
        for (int c = 0; c < CPB; ++c) {
            const float2 s = unpk2(acc[c]);
            const float p = s.x * s.x + s.y * s.y;
            sumP += p;
            if (sweep_angle[c0 + c] + 90 == n) sumD += p;
        }
    }

    // block reduction over 6 warps
#pragma unroll
    for (int off = 16; off > 0; off >>= 1) {
        sumP += __shfl_down_sync(0xffffffffu, sumP, off);
        sumD += __shfl_down_sync(0xffffffffu, sumD, off);
    }
    if ((tid & 31) == 0) { redP[tid >> 5] = sumP; redD[tid >> 5] = sumD; }
    __syncthreads();
    if (tid == 0) {
        float P = 0.f, D = 0.f;
#pragma unroll
        for (int i = 0; i < 6; ++i) { P += redP[i]; D += redD[i]; }
        g_P[blockIdx.x] = P;
        g_D[blockIdx.x] = D;
    }
}

// ---------------- finalize: out = K*S - (1+2K)*D, K = 0.1 ----------------
__global__ __launch_bounds__(256) void finalize_kernel(float* __restrict__ out)
{
    __shared__ float rP[SWEEP_BLOCKS], rD[SWEEP_BLOCKS];
    const int t = threadIdx.x;
    rP[t] = g_P[t];
    rD[t] = g_D[t];
    __syncthreads();
#pragma unroll
    for (int s = SWEEP_BLOCKS / 2; s > 0; s >>= 1) {
        if (t < s) { rP[t] += rP[t + s]; rD[t] += rD[t + s]; }
        __syncthreads();
    }
    if (t == 0) {
        // -(1+K)*D + K*(S - D) = K*S - (1+2K)*D
        out[0] = 0.1f * rP[0] - 1.2f * rD[0];
    }
}

// ---------------- launch ----------------
extern "C" void kernel_launch(void* const* d_in, const int* in_sizes, int n_in,
                              void* d_out, int out_size)
{
    (void)in_sizes; (void)n_in; (void)out_size;
    const float* w_re  = (const float*)d_in[0];
    const float* w_im  = (const float*)d_in[1];
    const float* th_re = (const float*)d_in[2];
    const float* th_im = (const float*)d_in[3];
    const float* G_re  = (const float*)d_in[4];
    const float* G_im  = (const float*)d_in[5];
    const float* st_re = (const float*)d_in[6];
    const float* st_im = (const float*)d_in[7];
    // d_in[8], d_in[9] (addw) unused: var term is multiplied by 0.0 and finite
    const int* sweep   = (const int*)d_in[10];

    dim3 g1(NTILES, ATILES, KSPLIT);   // (6, 2, 64)
    gemm1_kernel<<<g1, 256>>>(th_re, th_im, G_re, G_im, st_re, st_im);
    reduceB_kernel<<<(ARR * NANG + 255) / 256, 256>>>();
    sweep_kernel<<<SWEEP_BLOCKS, 192>>>(w_re, w_im, sweep);
    finalize_kernel<<<1, 256>>>((float*)d_out);
}

// round 6
// speedup vs baseline: 1.5270x; 1.5270x over previous
#include <cuda_runtime.h>
#include <cuda_bf16.h>

// ---------------- problem constants ----------------
#define CODE 2048
#define ARR  512
#define LENS 16384
#define NANG 181

// ---------------- GEMM config (mma.sync path, sm_100-safe) ----------------
#define K1     (2 * LENS)         // 32768 expanded K (re/im interleaved)
#define NPAD   384                // 2*181 padded
#define ZSPLIT 32
#define KCHUNK (K1 / ZSPLIT)      // 1024
#define NSTAGE (KCHUNK / 16)      // 64 stages of BK=16
#define MT     128                // CTA M tile
#define NT     128                // CTA N tile
#define ROWB   48                 // smem row stride bytes (32B data + 16B pad)
#define ARRB   (128 * ROWB)       // 6144 B per array tile
#define BUFB   (4 * ARRB)         // 24576 B per stage buffer

// ---------------- sweep config ----------------
#define CPB 4
#define SWEEP_BLOCKS (CODE / CPB)   // 512

// ---------------- device scratch ----------------
__device__ __align__(16) __nv_bfloat16 g_Ah[(size_t)ARR * K1];   // 32 MB
__device__ __align__(16) __nv_bfloat16 g_Al[(size_t)ARR * K1];   // 32 MB
__device__ __align__(16) __nv_bfloat16 g_Bh[(size_t)NPAD * K1];  // 24 MB
__device__ __align__(16) __nv_bfloat16 g_Bl[(size_t)NPAD * K1];  // 24 MB
__device__ __align__(16) float g_Dp[ZSPLIT][ARR * NPAD];         // 25 MB split-K partials
__device__ __align__(16) float g_Dfull[ARR * NPAD];
__device__ float g_P[SWEEP_BLOCKS];
__device__ float g_D[SWEEP_BLOCKS];

typedef unsigned long long u64;
typedef unsigned int u32;

// ---------------- PTX helpers ----------------
__device__ __forceinline__ u64 pk2(float lo, float hi) {
    u64 r;
    asm("mov.b64 %0, {%1, %2};" : "=l"(r) : "f"(lo), "f"(hi));
    return r;
}
__device__ __forceinline__ u64 ffma2(u64 a, u64 b, u64 c) {
    u64 d;
    asm("fma.rn.f32x2 %0, %1, %2, %3;" : "=l"(d) : "l"(a), "l"(b), "l"(c));
    return d;
}
__device__ __forceinline__ float2 unpk2(u64 v) {
    float lo, hi;
    asm("mov.b64 {%0, %1}, %2;" : "=f"(lo), "=f"(hi) : "l"(v));
    return make_float2(lo, hi);
}
__device__ __forceinline__ u32 smem_u32(const void* p) {
    u32 a;
    asm("{ .reg .u64 t; cvta.to.shared.u64 t, %1; cvt.u32.u64 %0, t; }" : "=r"(a) : "l"(p));
    return a;
}

#define CP_ASYNC16(dst, src) \
    asm volatile("cp.async.cg.shared.global [%0], [%1], 16;" :: "r"(dst), "l"(src))
#define CP_COMMIT() asm volatile("cp.async.commit_group;" ::: "memory")
#define CP_WAIT1()  asm volatile("cp.async.wait_group 1;" ::: "memory")
#define CP_WAIT0()  asm volatile("cp.async.wait_group 0;" ::: "memory")

#define LDSM_X4(r, addr) \
    asm volatile("ldmatrix.sync.aligned.m8n8.x4.shared.b16 {%0,%1,%2,%3}, [%4];" \
        : "=r"((r)[0]), "=r"((r)[1]), "=r"((r)[2]), "=r"((r)[3]) : "r"(addr))

#define LDS32(r, addr) \
    asm volatile("ld.shared.b32 %0, [%1];" : "=r"(r) : "r"(addr))

#define MMA16816(d, a, b0, b1) \
    asm volatile("mma.sync.aligned.m16n8k16.row.col.f32.bf16.bf16.f32 " \
        "{%0,%1,%2,%3}, {%4,%5,%6,%7}, {%8,%9}, {%0,%1,%2,%3};" \
        : "+f"((d)[0]), "+f"((d)[1]), "+f"((d)[2]), "+f"((d)[3]) \
        : "r"((a)[0]), "r"((a)[1]), "r"((a)[2]), "r"((a)[3]), "r"(b0), "r"(b1))

__device__ __forceinline__ void bf16split(float x, __nv_bfloat16& h, __nv_bfloat16& l) {
    h = __float2bfloat16_rn(x);
    l = __float2bfloat16_rn(x - __bfloat162float(h));
}

// ---------------- convA: A'' = (G * theta_n), re/im interleaved -> bf16 hi/lo ----------------
__global__ __launch_bounds__(256) void convA_kernel(
    const float* __restrict__ G_re, const float* __restrict__ G_im,
    const float* __restrict__ th_re, const float* __restrict__ th_im)
{
    const int idx = blockIdx.x * 256 + threadIdx.x;   // = m*LENS + k
    const int k = idx & (LENS - 1);
    float tr = th_re[k], ti = th_im[k];
    const float rn = rsqrtf(tr * tr + ti * ti);
    tr *= rn; ti *= rn;
    const float gr = G_re[idx], gi = G_im[idx];
    const float ar = gr * tr - gi * ti;
    const float ai = gr * ti + gi * tr;
    __nv_bfloat16 arh, arl, aih, ail;
    bf16split(ar, arh, arl);
    bf16split(ai, aih, ail);
    __nv_bfloat162 vh; vh.x = arh; vh.y = aih;
    __nv_bfloat162 vl; vl.x = arl; vl.y = ail;
    ((__nv_bfloat162*)g_Ah)[idx] = vh;   // A''[m,2k], A''[m,2k+1]
    ((__nv_bfloat162*)g_Al)[idx] = vl;
}

// ---------------- convB: steer[k][n] -> B''[j][K] transposed, hi/lo ----------------
// row j=2n: (sr,-si) at (2k,2k+1); row j=2n+1: (si,sr). Rows >= 362 zero.
// Grid (LENS/32=512, NPAD/64=6), 256 threads.
__global__ __launch_bounds__(256) void convB_kernel(
    const float* __restrict__ st_re, const float* __restrict__ st_im)
{
    __shared__ float sr[32][33], si[32][33];
    const int tid = threadIdx.x;
    const int k0 = blockIdx.x * 32;
    const int n0 = blockIdx.y * 32;

#pragma unroll
    for (int i = 0; i < 4; ++i) {
        const int id = tid + 256 * i;
        const int kk = id >> 5, nn = id & 31;
        const int n = n0 + nn;
        float vr = 0.f, vi = 0.f;
        if (n < NANG) {
            vr = st_re[(size_t)(k0 + kk) * NANG + n];
            vi = st_im[(size_t)(k0 + kk) * NANG + n];
        }
        sr[kk][nn] = vr;
        si[kk][nn] = vi;
    }
    __syncthreads();

#pragma unroll
    for (int i = 0; i < 8; ++i) {
        const int id = tid + 256 * i;          // 2048: 64 j-rows x 32 k
        const int kl = id & 31;
        const int jl = id >> 5;
        const int nl = jl >> 1;
        const bool ev = !(jl & 1);
        const float vr = sr[kl][nl], vi = si[kl][nl];
        const float c0 = ev ? vr : vi;
        const float c1 = ev ? -vi : vr;
        __nv_bfloat16 c0h, c0l, c1h, c1l;
        bf16split(c0, c0h, c0l);
        bf16split(c1, c1h, c1l);
        const size_t off2 = (size_t)(n0 * 2 + jl) * (K1 / 2) + (k0 + kl);
        __nv_bfloat162 vh; vh.x = c0h; vh.y = c1h;
        __nv_bfloat162 vl; vl.x = c0l; vl.y = c1l;
        ((__nv_bfloat162*)g_Bh)[off2] = vh;
        ((__nv_bfloat162*)g_Bl)[off2] = vl;
    }
}

// ---------------- GEMM: D += Ah@Bh^T + Al@Bh^T + Ah@Bl^T via mma.sync ----------------
// Grid (ARR/MT=4, NPAD/NT=3, ZSPLIT=32) = 384 CTAs, 256 threads (8 warps, 2M x 4N).
__global__ __launch_bounds__(256, 1) void gemm_mma_kernel()
{
    // [2 buffers][4 arrays: Ah,Al,Bh,Bl][128 rows x 48B]
    __shared__ __align__(16) unsigned char sT[2][4][ARRB];

    const int tid = threadIdx.x;
    const int wid = tid >> 5;
    const int lane = tid & 31;
    const int m0 = blockIdx.x * MT;
    const int n0 = blockIdx.y * NT;
    const int bz = blockIdx.z;
    const int kc0 = bz * KCHUNK;

    const u32 smbase = smem_u32(sT);

    // ---- cp.async addressing: thread handles row r = tid>>1, half c = tid&1 in all 4 arrays
    const int r = tid >> 1;
    const int c = tid & 1;
    const u32 dst_off = (u32)(r * ROWB + c * 16);
    const __nv_bfloat16* srcp[4];
    srcp[0] = g_Ah + (size_t)(m0 + r) * K1 + kc0 + c * 8;
    srcp[1] = g_Al + (size_t)(m0 + r) * K1 + kc0 + c * 8;
    srcp[2] = g_Bh + (size_t)(n0 + r) * K1 + kc0 + c * 8;
    srcp[3] = g_Bl + (size_t)(n0 + r) * K1 + kc0 + c * 8;

    // ---- A fragment via ldmatrix (canonical x4 -> a0..a3)
    const int wm = wid >> 2;          // 0..1 -> 64 rows of M
    const int wn = wid & 3;           // 0..3 -> 32 cols of N
    const int lrow = lane & 15;
    const int lbyte = (lane >> 4) * 16;
    const u32 a_off = (u32)((wm * 64 + lrow) * ROWB + lbyte);   // + mi*16*ROWB

    // ---- B fragment via explicit LDS.32 at PTX-mandated coords:
    // b0: k = (lane%4)*2 (+1 in hi half), n = lane/4; b1: same n, k += 8.
    const u32 b_off = (u32)((wn * 32 + (lane >> 2)) * ROWB + (lane & 3) * 4);  // + ni*8*ROWB

    float D[4][4][4];
#pragma unroll
    for (int mi = 0; mi < 4; ++mi)
#pragma unroll
        for (int ni = 0; ni < 4; ++ni)
#pragma unroll
            for (int e = 0; e < 4; ++e) D[mi][ni][e] = 0.f;

    // ---- prologue: stage 0 into buffer 0
#pragma unroll
    for (int a = 0; a < 4; ++a)
        CP_ASYNC16(smbase + 0 * BUFB + a * ARRB + dst_off, srcp[a]);
    CP_COMMIT();

#pragma unroll 1
    for (int s = 0; s < NSTAGE; ++s) {
        if (s + 1 < NSTAGE) {
            const u32 nb = smbase + ((s + 1) & 1) * BUFB + dst_off;
#pragma unroll
            for (int a = 0; a < 4; ++a)
                CP_ASYNC16(nb + a * ARRB, srcp[a] + (size_t)(s + 1) * 16);
            CP_COMMIT();
            CP_WAIT1();
        } else {
            CP_WAIT0();
        }
        __syncthreads();

        const u32 buf = smbase + (s & 1) * BUFB;

        u32 Ahf[4][4], Alf[4][4];
#pragma unroll
        for (int mi = 0; mi < 4; ++mi) {
            LDSM_X4(Ahf[mi], buf + 0 * ARRB + a_off + mi * (16 * ROWB));
            LDSM_X4(Alf[mi], buf + 1 * ARRB + a_off + mi * (16 * ROWB));
        }

        u32 Bh0[4], Bh1[4], Bl0[4], Bl1[4];
        const u32 bh_base = buf + 2 * ARRB + b_off;
        const u32 bl_base = buf + 3 * ARRB + b_off;
#pragma unroll
        for (int ni = 0; ni < 4; ++ni) {
            LDS32(Bh0[ni], bh_base + ni * (8 * ROWB));        // k 0-7 pair
            LDS32(Bh1[ni], bh_base + ni * (8 * ROWB) + 16);   // k 8-15 pair
            LDS32(Bl0[ni], bl_base + ni * (8 * ROWB));
            LDS32(Bl1[ni], bl_base + ni * (8 * ROWB) + 16);
        }

#pragma unroll
        for (int mi = 0; mi < 4; ++mi) {
#pragma unroll
            for (int ni = 0; ni < 4; ++ni) {
                MMA16816(D[mi][ni], Ahf[mi], Bh0[ni], Bh1[ni]);
                MMA16816(D[mi][ni], Alf[mi], Bh0[ni], Bh1[ni]);
                MMA16816(D[mi][ni], Ahf[mi], Bl0[ni], Bl1[ni]);
            }
        }
        __syncthreads();
    }

    // ---- epilogue: write split-K partial tile (disjoint per bz -> deterministic)
    float* __restrict__ out = g_Dp[bz];
    const int rbase = m0 + wm * 64 + (lane >> 2);
    const int cbase = n0 + wn * 32 + (lane & 3) * 2;
#pragma unroll
    for (int mi = 0; mi < 4; ++mi) {
#pragma unroll
        for (int ni = 0; ni < 4; ++ni) {
            const int row = rbase + mi * 16;
            const int col = cbase + ni * 8;
            float2 v0; v0.x = D[mi][ni][0]; v0.y = D[mi][ni][1];
            float2 v1; v1.x = D[mi][ni][2]; v1.y = D[mi][ni][3];
            *(float2*)(out + (size_t)row * NPAD + col) = v0;
            *(float2*)(out + (size_t)(row + 8) * NPAD + col) = v1;
        }
    }
}

// ---------------- reduce split-K partials ----------------
__global__ __launch_bounds__(256) void reduceD_kernel()
{
    const int i = blockIdx.x * 256 + threadIdx.x;
    float s = 0.f;
#pragma unroll 8
    for (int z = 0; z < ZSPLIT; ++z) s += g_Dp[z][i];
    g_Dfull[i] = s;
}

// ---------------- sweep: sout = w_n @ B, fused |.|^2 + diag gather ----------------
__global__ __launch_bounds__(192) void sweep_kernel(
    const float* __restrict__ w_re, const float* __restrict__ w_im,
    const int* __restrict__ sweep_angle)
{
    __shared__ ulonglong2 sw[CPB * ARR];   // {(wr,wr),(wi,wi)} pre-duplicated, 32 KB
    __shared__ float redP[6], redD[6];

    const int tid = threadIdx.x;
    const int c0 = blockIdx.x * CPB;

    for (int idx = tid; idx < CPB * ARR; idx += 192) {
        const int cc = idx >> 9;
        const int a = idx & (ARR - 1);
        const float wr = w_re[(size_t)(c0 + cc) * ARR + a];
        const float wi = w_im[(size_t)(c0 + cc) * ARR + a];
        const float rn = rsqrtf(wr * wr + wi * wi);
        ulonglong2 v;
        v.x = pk2(wr * rn, wr * rn);
        v.y = pk2(wi * rn, wi * rn);
        sw[idx] = v;
    }
    __syncthreads();

    float sumP = 0.f, sumD = 0.f;
    const int n = tid;
    if (n < NANG) {
        const u64* __restrict__ Brow = (const u64*)g_Dfull;   // (re,im) pairs, row = NPAD/2 u64
        u64 acc[CPB];
#pragma unroll
        for (int cc = 0; cc < CPB; ++cc) acc[cc] = pk2(0.f, 0.f);

#pragma unroll 4
        for (int a = 0; a < ARR; ++a) {
            const u64 bp = Brow[(size_t)a * (NPAD / 2) + n];   // (br, bi) coalesced
            const float2 b2 = unpk2(bp);
            const u64 bq = pk2(-b2.y, b2.x);                   // (-bi, br)
#pragma unroll
            for (int cc = 0; cc < CPB; ++cc) {
                const ulonglong2 wv = sw[cc * ARR + a];
                acc[cc] = ffma2(wv.x, bp, ffma2(wv.y, bq, acc[cc]));
            }
        }
#pragma unroll
        for (int cc = 0; cc < CPB; ++cc) {
            const float2 s = unpk2(acc[cc]);
            const float p = s.x * s.x + s.y * s.y;
            sumP += p;
            if (sweep_angle[c0 + cc] + 90 == n) sumD += p;
        }
    }

#pragma unroll
    for (int off = 16; off > 0; off >>= 1) {
        sumP += __shfl_down_sync(0xffffffffu, sumP, off);
        sumD += __shfl_down_sync(0xffffffffu, sumD, off);
    }
    if ((tid & 31) == 0) { redP[tid >> 5] = sumP; redD[tid >> 5] = sumD; }
    __syncthreads();
    if (tid == 0) {
        float P = 0.f, Dd = 0.f;
#pragma unroll
        for (int i = 0; i < 6; ++i) { P += redP[i]; Dd += redD[i]; }
        g_P[blockIdx.x] = P;
        g_D[blockIdx.x] = Dd;
    }
}

// ---------------- finalize: out = K*S - (1+2K)*D, K = 0.1 ----------------
__global__ __launch_bounds__(512) void finalize_kernel(float* __restrict__ out)
{
    __shared__ float rP[SWEEP_BLOCKS], rD[SWEEP_BLOCKS];
    const int t = threadIdx.x;
    rP[t] = g_P[t];
    rD[t] = g_D[t];
    __syncthreads();
#pragma unroll
    for (int s = SWEEP_BLOCKS / 2; s > 0; s >>= 1) {
        if (t < s) { rP[t] += rP[t + s]; rD[t] += rD[t + s]; }
        __syncthreads();
    }
    if (t == 0) out[0] = 0.1f * rP[0] - 1.2f * rD[0];
}

// ---------------- launch ----------------
extern "C" void kernel_launch(void* const* d_in, const int* in_sizes, int n_in,
                              void* d_out, int out_size)
{
    (void)in_sizes; (void)n_in; (void)out_size;
    const float* w_re  = (const float*)d_in[0];
    const float* w_im  = (const float*)d_in[1];
    const float* th_re = (const float*)d_in[2];
    const float* th_im = (const float*)d_in[3];
    const float* G_re  = (const float*)d_in[4];
    const float* G_im  = (const float*)d_in[5];
    const float* st_re = (const float*)d_in[6];
    const float* st_im = (const float*)d_in[7];
    const int* sweep   = (const int*)d_in[10];   // addw (d_in[8],[9]) unused: var term * 0.0

    convA_kernel<<<(ARR * LENS) / 256, 256>>>(G_re, G_im, th_re, th_im);
    convB_kernel<<<dim3(LENS / 32, NPAD / 64, 1), 256>>>(st_re, st_im);
    gemm_mma_kernel<<<dim3(ARR / MT, NPAD / NT, ZSPLIT), 256>>>();
    reduceD_kernel<<<(ARR * NPAD) / 256, 256>>>();
    sweep_kernel<<<SWEEP_BLOCKS, 192>>>(w_re, w_im, sweep);
    finalize_kernel<<<1, SWEEP_BLOCKS>>>((float*)d_out);
}

// round 7
// speedup vs baseline: 1.7644x; 1.1555x over previous
#include <cuda_runtime.h>
#include <cuda_bf16.h>

// ---------------- problem constants ----------------
#define CODE 2048
#define ARR  512
#define LENS 16384
#define NANG 181

// ---------------- GEMM config (mma.sync path, sm_100-safe) ----------------
#define K1     (2 * LENS)         // 32768 expanded K (re/im interleaved)
#define NPAD   384                // 2*181 padded
#define ZSPLIT 32
#define KCHUNK (K1 / ZSPLIT)      // 1024
#define NSTAGE (KCHUNK / 16)      // 64 stages of BK=16
#define MT     128                // CTA M tile
#define NT     128                // CTA N tile
#define STAGEB 16384              // 128 rows x 128B unified tile
#define SBUF   3                  // pipeline depth (3 x 16KB = 48KB static)

// ---------------- sweep config ----------------
#define CPB 4
#define SWEEP_BLOCKS (CODE / CPB)   // 512

// ---------------- device scratch ----------------
__device__ __align__(16) __nv_bfloat16 g_Ah[(size_t)ARR * K1];   // 32 MB
__device__ __align__(16) __nv_bfloat16 g_Al[(size_t)ARR * K1];   // 32 MB
__device__ __align__(16) __nv_bfloat16 g_Bh[(size_t)NPAD * K1];  // 24 MB
__device__ __align__(16) __nv_bfloat16 g_Bl[(size_t)NPAD * K1];  // 24 MB
__device__ __align__(16) float g_Dp[ZSPLIT][ARR * NPAD];         // 25 MB split-K partials
__device__ __align__(16) float g_Dfull[ARR * NPAD];
__device__ float g_P[SWEEP_BLOCKS];
__device__ float g_D[SWEEP_BLOCKS];

typedef unsigned long long u64;
typedef unsigned int u32;

// ---------------- PTX helpers ----------------
__device__ __forceinline__ u64 pk2(float lo, float hi) {
    u64 r;
    asm("mov.b64 %0, {%1, %2};" : "=l"(r) : "f"(lo), "f"(hi));
    return r;
}
__device__ __forceinline__ u64 ffma2(u64 a, u64 b, u64 c) {
    u64 d;
    asm("fma.rn.f32x2 %0, %1, %2, %3;" : "=l"(d) : "l"(a), "l"(b), "l"(c));
    return d;
}
__device__ __forceinline__ float2 unpk2(u64 v) {
    float lo, hi;
    asm("mov.b64 {%0, %1}, %2;" : "=f"(lo), "=f"(hi) : "l"(v));
    return make_float2(lo, hi);
}
__device__ __forceinline__ u32 smem_u32(const void* p) {
    u32 a;
    asm("{ .reg .u64 t; cvta.to.shared.u64 t, %1; cvt.u32.u64 %0, t; }" : "=r"(a) : "l"(p));
    return a;
}

#define CP_ASYNC16(dst, src) \
    asm volatile("cp.async.cg.shared.global [%0], [%1], 16;" :: "r"(dst), "l"(src))
#define CP_COMMIT() asm volatile("cp.async.commit_group;" ::: "memory")
#define CP_WAIT1()  asm volatile("cp.async.wait_group 1;" ::: "memory")
#define CP_WAIT0()  asm volatile("cp.async.wait_group 0;" ::: "memory")

#define LDSM_X4(r, addr) \
    asm volatile("ldmatrix.sync.aligned.m8n8.x4.shared.b16 {%0,%1,%2,%3}, [%4];" \
        : "=r"((r)[0]), "=r"((r)[1]), "=r"((r)[2]), "=r"((r)[3]) : "r"(addr))

#define MMA16816(d, a, b0, b1) \
    asm volatile("mma.sync.aligned.m16n8k16.row.col.f32.bf16.bf16.f32 " \
        "{%0,%1,%2,%3}, {%4,%5,%6,%7}, {%8,%9}, {%0,%1,%2,%3};" \
        : "+f"((d)[0]), "+f"((d)[1]), "+f"((d)[2]), "+f"((d)[3]) \
        : "r"((a)[0]), "r"((a)[1]), "r"((a)[2]), "r"((a)[3]), "r"(b0), "r"(b1))

__device__ __forceinline__ void bf16split(float x, __nv_bfloat16& h, __nv_bfloat16& l) {
    h = __float2bfloat16_rn(x);
    l = __float2bfloat16_rn(x - __bfloat162float(h));
}

// ---------------- convA: A'' = (G * theta_n), re/im interleaved -> bf16 hi/lo ----------------
__global__ __launch_bounds__(256) void convA_kernel(
    const float* __restrict__ G_re, const float* __restrict__ G_im,
    const float* __restrict__ th_re, const float* __restrict__ th_im)
{
    const int idx = blockIdx.x * 256 + threadIdx.x;   // = m*LENS + k
    const int k = idx & (LENS - 1);
    float tr = th_re[k], ti = th_im[k];
    const float rn = rsqrtf(tr * tr + ti * ti);
    tr *= rn; ti *= rn;
    const float gr = G_re[idx], gi = G_im[idx];
    const float ar = gr * tr - gi * ti;
    const float ai = gr * ti + gi * tr;
    __nv_bfloat16 arh, arl, aih, ail;
    bf16split(ar, arh, arl);
    bf16split(ai, aih, ail);
    __nv_bfloat162 vh; vh.x = arh; vh.y = aih;
    __nv_bfloat162 vl; vl.x = arl; vl.y = ail;
    ((__nv_bfloat162*)g_Ah)[idx] = vh;   // A''[m,2k], A''[m,2k+1]
    ((__nv_bfloat162*)g_Al)[idx] = vl;
}

// ---------------- convB: steer[k][n] -> B''[j][K] transposed, hi/lo ----------------
// row j=2n: (sr,-si) at (2k,2k+1); row j=2n+1: (si,sr). Rows >= 362 zero.
__global__ __launch_bounds__(256) void convB_kernel(
    const float* __restrict__ st_re, const float* __restrict__ st_im)
{
    __shared__ float sr[32][33], si[32][33];
    const int tid = threadIdx.x;
    const int k0 = blockIdx.x * 32;
    const int n0 = blockIdx.y * 32;

#pragma unroll
    for (int i = 0; i < 4; ++i) {
        const int id = tid + 256 * i;
        const int kk = id >> 5, nn = id & 31;
        const int n = n0 + nn;
        float vr = 0.f, vi = 0.f;
        if (n < NANG) {
            vr = st_re[(size_t)(k0 + kk) * NANG + n];
            vi = st_im[(size_t)(k0 + kk) * NANG + n];
        }
        sr[kk][nn] = vr;
        si[kk][nn] = vi;
    }
    __syncthreads();

#pragma unroll
    for (int i = 0; i < 8; ++i) {
        const int id = tid + 256 * i;          // 2048: 64 j-rows x 32 k
        const int kl = id & 31;
        const int jl = id >> 5;
        const int nl = jl >> 1;
        const bool ev = !(jl & 1);
        const float vr = sr[kl][nl], vi = si[kl][nl];
        const float c0 = ev ? vr : vi;
        const float c1 = ev ? -vi : vr;
        __nv_bfloat16 c0h, c0l, c1h, c1l;
        bf16split(c0, c0h, c0l);
        bf16split(c1, c1h, c1l);
        const size_t off2 = (size_t)(n0 * 2 + jl) * (K1 / 2) + (k0 + kl);
        __nv_bfloat162 vh; vh.x = c0h; vh.y = c1h;
        __nv_bfloat162 vl; vl.x = c0l; vl.y = c1l;
        ((__nv_bfloat162*)g_Bh)[off2] = vh;
        ((__nv_bfloat162*)g_Bl)[off2] = vl;
    }
}

// ---------------- GEMM: D += Ah@Bh^T + Al@Bh^T + Ah@Bl^T via mma.sync ----------------
// Grid (ARR/MT=4, NPAD/NT=3, ZSPLIT=32) = 384 CTAs, 256 threads (8 warps, 2M x 4N).
// Unified stage tile: 128 rows x 128B = [Ah 32B | Al 32B | Bh 32B | Bl 32B] per row,
// XOR-swizzled 16B granules (g ^= row&7) -> conflict-free LDSM + full-width rows.
// 3-stage cp.async pipeline, ONE __syncthreads per stage.
__global__ __launch_bounds__(256, 2) void gemm_mma_kernel()
{
    __shared__ __align__(128) unsigned char sT[SBUF][STAGEB];   // 48 KB

    const int tid = threadIdx.x;
    const int wid = tid >> 5;
    const int lane = tid & 31;
    const int m0 = blockIdx.x * MT;
    const int n0 = blockIdx.y * NT;
    const int bz = blockIdx.z;
    const int kc0 = bz * KCHUNK;

    const u32 smbase = smem_u32(sT);

    // ---- cp.async addressing: thread -> row r = tid>>1, 16B-half c = tid&1, all 4 parts
    const int r = tid >> 1;
    const int cc = tid & 1;
    u32 doff[4];
#pragma unroll
    for (int p = 0; p < 4; ++p)
        doff[p] = (u32)(r * 128 + (((p * 2 + cc) ^ (r & 7)) << 4));
    const __nv_bfloat16* srcp[4];
    srcp[0] = g_Ah + (size_t)(m0 + r) * K1 + kc0 + cc * 8;
    srcp[1] = g_Al + (size_t)(m0 + r) * K1 + kc0 + cc * 8;
    srcp[2] = g_Bh + (size_t)(n0 + r) * K1 + kc0 + cc * 8;
    srcp[3] = g_Bl + (size_t)(n0 + r) * K1 + kc0 + cc * 8;

    const int wm = wid >> 2;          // 0..1 -> 64 rows of M
    const int wn = wid & 3;           // 0..3 -> 32 cols of N

    float D[4][4][4];
#pragma unroll
    for (int mi = 0; mi < 4; ++mi)
#pragma unroll
        for (int ni = 0; ni < 4; ++ni)
#pragma unroll
            for (int e = 0; e < 4; ++e) D[mi][ni][e] = 0.f;

    // ---- prologue: stages 0,1
#pragma unroll
    for (int st = 0; st < 2; ++st) {
        const u32 b = smbase + st * STAGEB;
#pragma unroll
        for (int p = 0; p < 4; ++p)
            CP_ASYNC16(b + doff[p], srcp[p] + st * 16);
        CP_COMMIT();
    }

#pragma unroll 1
    for (int s = 0; s < NSTAGE; ++s) {
        if (s + 1 < NSTAGE) { CP_WAIT1(); } else { CP_WAIT0(); }
        __syncthreads();     // stage s visible to all; buf (s+2)%3 free to overwrite

        if (s + 2 < NSTAGE) {
            const u32 b = smbase + ((s + 2) % SBUF) * STAGEB;
#pragma unroll
            for (int p = 0; p < 4; ++p)
                CP_ASYNC16(b + doff[p], srcp[p] + (s + 2) * 16);
            CP_COMMIT();
        }

        const u32 buf = smbase + (s % SBUF) * STAGEB;

        // B fragments: ldmatrix.x4, pairing (r0,r2)/(r1,r3)
        u32 Bh[2][4], Bl[2][4];
#pragma unroll
        for (int nc = 0; nc < 2; ++nc) {
            const int row = wn * 32 + nc * 16 + (lane & 7) + ((lane >> 3) & 1) * 8;
            const u32 gh = (u32)((4 + (lane >> 4)) ^ (row & 7));
            const u32 gl = (u32)((6 + (lane >> 4)) ^ (row & 7));
            LDSM_X4(Bh[nc], buf + row * 128 + (gh << 4));
            LDSM_X4(Bl[nc], buf + row * 128 + (gl << 4));
        }

#pragma unroll
        for (int mi = 0; mi < 4; ++mi) {
            const int row = wm * 64 + mi * 16 + (lane & 15);
            const u32 gh = (u32)((0 + (lane >> 4)) ^ (row & 7));
            const u32 gl = (u32)((2 + (lane >> 4)) ^ (row & 7));
            u32 Ahf[4], Alf[4];
            LDSM_X4(Ahf, buf + row * 128 + (gh << 4));
            LDSM_X4(Alf, buf + row * 128 + (gl << 4));
#pragma unroll
            for (int ni = 0; ni < 4; ++ni) {
                const u32 b0 = Bh[ni >> 1][ni & 1], b1 = Bh[ni >> 1][(ni & 1) + 2];
                const u32 c0 = Bl[ni >> 1][ni & 1], c1 = Bl[ni >> 1][(ni & 1) + 2];
                MMA16816(D[mi][ni], Ahf, b0, b1);
                MMA16816(D[mi][ni], Alf, b0, b1);
                MMA16816(D[mi][ni], Ahf, c0, c1);
            }
        }
    }

    // ---- epilogue: write split-K partial tile (disjoint per bz -> deterministic)
    float* __restrict__ out = g_Dp[bz];
    const int rbase = m0 + wm * 64 + (lane >> 2);
    const int cbase = n0 + wn * 32 + (lane & 3) * 2;
#pragma unroll
    for (int mi = 0; mi < 4; ++mi) {
#pragma unroll
        for (int ni = 0; ni < 4; ++ni) {
            const int row = rbase + mi * 16;
            const int col = cbase + ni * 8;
            float2 v0; v0.x = D[mi][ni][0]; v0.y = D[mi][ni][1];
            float2 v1; v1.x = D[mi][ni][2]; v1.y = D[mi][ni][3];
            *(float2*)(out + (size_t)row * NPAD + col) = v0;
            *(float2*)(out + (size_t)(row + 8) * NPAD + col) = v1;
        }
    }
}

// ---------------- reduce split-K partials ----------------
__global__ __launch_bounds__(256) void reduceD_kernel()
{
    const int i = blockIdx.x * 256 + threadIdx.x;
    float s = 0.f;
#pragma unroll 8
    for (int z = 0; z < ZSPLIT; ++z) s += g_Dp[z][i];
    g_Dfull[i] = s;
}

// ---------------- sweep: sout = w_n @ B, fused |.|^2 + diag gather ----------------
__global__ __launch_bounds__(192) void sweep_kernel(
    const float* __restrict__ w_re, const float* __restrict__ w_im,
    const int* __restrict__ sweep_angle)
{
    __shared__ ulonglong2 sw[CPB * ARR];   // {(wr,wr),(wi,wi)} pre-duplicated, 32 KB
    __shared__ float redP[6], redD[6];

    const int tid = threadIdx.x;
    const int c0 = blockIdx.x * CPB;

    for (int idx = tid; idx < CPB * ARR; idx += 192) {
        const int ci = idx >> 9;
        const int a = idx & (ARR - 1);
        const float wr = w_re[(size_t)(c0 + ci) * ARR + a];
        const float wi = w_im[(size_t)(c0 + ci) * ARR + a];
        const float rn = rsqrtf(wr * wr + wi * wi);
        ulonglong2 v;
        v.x = pk2(wr * rn, wr * rn);
        v.y = pk2(wi * rn, wi * rn);
        sw[idx] = v;
    }
    __syncthreads();

    float sumP = 0.f, sumD = 0.f;
    const int n = tid;
    if (n < NANG) {
        const u64* __restrict__ Brow = (const u64*)g_Dfull;   // (re,im) pairs, row = NPAD/2 u64
        u64 acc[CPB];
#pragma unroll
        for (int ci = 0; ci < CPB; ++ci) acc[ci] = pk2(0.f, 0.f);

#pragma unroll 4
        for (int a = 0; a < ARR; ++a) {
            const u64 bp = Brow[(size_t)a * (NPAD / 2) + n];   // (br, bi) coalesced
            const float2 b2 = unpk2(bp);
            const u64 bq = pk2(-b2.y, b2.x);                   // (-bi, br)
#pragma unroll
            for (int ci = 0; ci < CPB; ++ci) {
                const ulonglong2 wv = sw[ci * ARR + a];
                acc[ci] = ffma2(wv.x, bp, ffma2(wv.y, bq, acc[ci]));
            }
        }
#pragma unroll
        for (int ci = 0; ci < CPB; ++ci) {
            const float2 s = unpk2(acc[ci]);
            const float p = s.x * s.x + s.y * s.y;
            sumP += p;
            if (sweep_angle[c0 + ci] + 90 == n) sumD += p;
        }
    }

#pragma unroll
    for (int off = 16; off > 0; off >>= 1) {
        sumP += __shfl_down_sync(0xffffffffu, sumP, off);
        sumD += __shfl_down_sync(0xffffffffu, sumD, off);
    }
    if ((tid & 31) == 0) { redP[tid >> 5] = sumP; redD[tid >> 5] = sumD; }
    __syncthreads();
    if (tid == 0) {
        float P = 0.f, Dd = 0.f;
#pragma unroll
        for (int i = 0; i < 6; ++i) { P += redP[i]; Dd += redD[i]; }
        g_P[blockIdx.x] = P;
        g_D[blockIdx.x] = Dd;
    }
}

// ---------------- finalize: out = K*S - (1+2K)*D, K = 0.1 ----------------
__global__ __launch_bounds__(512) void finalize_kernel(float* __restrict__ out)
{
    __shared__ float rP[SWEEP_BLOCKS], rD[SWEEP_BLOCKS];
    const int t = threadIdx.x;
    rP[t] = g_P[t];
    rD[t] = g_D[t];
    __syncthreads();
#pragma unroll
    for (int s = SWEEP_BLOCKS / 2; s > 0; s >>= 1) {
        if (t < s) { rP[t] += rP[t + s]; rD[t] += rD[t + s]; }
        __syncthreads();
    }
    if (t == 0) out[0] = 0.1f * rP[0] - 1.2f * rD[0];
}

// ---------------- launch ----------------
extern "C" void kernel_launch(void* const* d_in, const int* in_sizes, int n_in,
                              void* d_out, int out_size)
{
    (void)in_sizes; (void)n_in; (void)out_size;
    const float* w_re  = (const float*)d_in[0];
    const float* w_im  = (const float*)d_in[1];
    const float* th_re = (const float*)d_in[2];
    const float* th_im = (const float*)d_in[3];
    const float* G_re  = (const float*)d_in[4];
    const float* G_im  = (const float*)d_in[5];
    const float* st_re = (const float*)d_in[6];
    const float* st_im = (const float*)d_in[7];
    const int* sweep   = (const int*)d_in[10];   // addw (d_in[8],[9]) unused: var term * 0.0

    convA_kernel<<<(ARR * LENS) / 256, 256>>>(G_re, G_im, th_re, th_im);
    convB_kernel<<<dim3(LENS / 32, NPAD / 64, 1), 256>>>(st_re, st_im);
    gemm_mma_kernel<<<dim3(ARR / MT, NPAD / NT, ZSPLIT), 256>>>();
    reduceD_kernel<<<(ARR * NPAD) / 256, 256>>>();
    sweep_kernel<<<SWEEP_BLOCKS, 192>>>(w_re, w_im, sweep);
    finalize_kernel<<<1, SWEEP_BLOCKS>>>((float*)d_out);
}

// round 10
// speedup vs baseline: 2.6760x; 1.5166x over previous
#include <cuda_runtime.h>
#include <cuda_bf16.h>

// ---------------- problem constants ----------------
#define CODE 2048
#define ARR  512
#define LENS 16384
#define NANG 181

// ---------------- GEMM config (mma.sync path, sm_100-safe, pure bf16) ----------------
#define K1     (2 * LENS)         // 32768 expanded K (re/im interleaved)
#define NPAD   384                // 2*181 padded
#define ZSPLIT 32
#define KCHUNK (K1 / ZSPLIT)      // 1024
#define BK     32                 // K per stage
#define NSTAGE (KCHUNK / BK)      // 32 stages
#define MT     128                // CTA M tile
#define NT     128                // CTA N tile
#define STAGEB 16384              // 128 rows x 128B = [A 64B | B 64B] per row
#define SBUF   3                  // pipeline depth (48KB static)

// ---------------- sweep config ----------------
#define CPB 8
#define SWEEP_BLOCKS (CODE / CPB)   // 256

// ---------------- device scratch ----------------
__device__ __align__(16) __nv_bfloat16 g_Ah[(size_t)ARR * K1];   // 32 MB
__device__ __align__(16) __nv_bfloat16 g_Bh[(size_t)NPAD * K1];  // 24 MB
__device__ __align__(16) float g_Dp[ZSPLIT][ARR * NPAD];         // 25 MB split-K partials
__device__ __align__(16) float g_Dfull[ARR * NPAD];
__device__ float g_P[SWEEP_BLOCKS];
__device__ float g_D[SWEEP_BLOCKS];

typedef unsigned long long u64;
typedef unsigned int u32;

// ---------------- PTX helpers ----------------
__device__ __forceinline__ u64 pk2(float lo, float hi) {
    u64 r;
    asm("mov.b64 %0, {%1, %2};" : "=l"(r) : "f"(lo), "f"(hi));
    return r;
}
__device__ __forceinline__ u64 ffma2(u64 a, u64 b, u64 c) {
    u64 d;
    asm("fma.rn.f32x2 %0, %1, %2, %3;" : "=l"(d) : "l"(a), "l"(b), "l"(c));
    return d;
}
__device__ __forceinline__ float2 unpk2(u64 v) {
    float lo, hi;
    asm("mov.b64 {%0, %1}, %2;" : "=f"(lo), "=f"(hi) : "l"(v));
    return make_float2(lo, hi);
}
__device__ __forceinline__ u32 smem_u32(const void* p) {
    u32 a;
    asm("{ .reg .u64 t; cvta.to.shared.u64 t, %1; cvt.u32.u64 %0, t; }" : "=r"(a) : "l"(p));
    return a;
}

#define CP_ASYNC16(dst, src) \
    asm volatile("cp.async.cg.shared.global [%0], [%1], 16;" :: "r"(dst), "l"(src))
#define CP_COMMIT() asm volatile("cp.async.commit_group;" ::: "memory")
#define CP_WAIT1()  asm volatile("cp.async.wait_group 1;" ::: "memory")
#define CP_WAIT0()  asm volatile("cp.async.wait_group 0;" ::: "memory")

#define LDSM_X4(r, addr) \
    asm volatile("ldmatrix.sync.aligned.m8n8.x4.shared.b16 {%0,%1,%2,%3}, [%4];" \
        : "=r"((r)[0]), "=r"((r)[1]), "=r"((r)[2]), "=r"((r)[3]) : "r"(addr))

#define MMA16816(d, a, b0, b1) \
    asm volatile("mma.sync.aligned.m16n8k16.row.col.f32.bf16.bf16.f32 " \
        "{%0,%1,%2,%3}, {%4,%5,%6,%7}, {%8,%9}, {%0,%1,%2,%3};" \
        : "+f"((d)[0]), "+f"((d)[1]), "+f"((d)[2]), "+f"((d)[3]) \
        : "r"((a)[0]), "r"((a)[1]), "r"((a)[2]), "r"((a)[3]), "r"(b0), "r"(b1))

// ---------------- convA: A'' = (G * theta_n), re/im interleaved -> bf16 ----------------
__global__ __launch_bounds__(256) void convA_kernel(
    const float* __restrict__ G_re, const float* __restrict__ G_im,
    const float* __restrict__ th_re, const float* __restrict__ th_im)
{
    const int idx = blockIdx.x * 256 + threadIdx.x;   // = m*LENS + k
    const int k = idx & (LENS - 1);
    float tr = th_re[k], ti = th_im[k];
    const float rn = rsqrtf(tr * tr + ti * ti);
    tr *= rn; ti *= rn;
    const float gr = G_re[idx], gi = G_im[idx];
    const float ar = gr * tr - gi * ti;
    const float ai = gr * ti + gi * tr;
    __nv_bfloat162 v;
    v.x = __float2bfloat16_rn(ar);
    v.y = __float2bfloat16_rn(ai);
    ((__nv_bfloat162*)g_Ah)[idx] = v;   // A''[m,2k], A''[m,2k+1]
}

// ---------------- convB: steer[k][n] -> B''[j][K] transposed bf16 ----------------
// row j=2n: (sr,-si) at (2k,2k+1); row j=2n+1: (si,sr). Rows >= 362 zero.
__global__ __launch_bounds__(256) void convB_kernel(
    const float* __restrict__ st_re, const float* __restrict__ st_im)
{
    __shared__ float sr[32][33], si[32][33];
    const int tid = threadIdx.x;
    const int k0 = blockIdx.x * 32;
    const int n0 = blockIdx.y * 32;

#pragma unroll
    for (int i = 0; i < 4; ++i) {
        const int id = tid + 256 * i;
        const int kk = id >> 5, nn = id & 31;
        const int n = n0 + nn;
        float vr = 0.f, vi = 0.f;
        if (n < NANG) {
            vr = st_re[(size_t)(k0 + kk) * NANG + n];
            vi = st_im[(size_t)(k0 + kk) * NANG + n];
        }
        sr[kk][nn] = vr;
        si[kk][nn] = vi;
    }
    __syncthreads();

#pragma unroll
    for (int i = 0; i < 8; ++i) {
        const int id = tid + 256 * i;          // 2048: 64 j-rows x 32 k
        const int kl = id & 31;
        const int jl = id >> 5;
        const int nl = jl >> 1;
        const bool ev = !(jl & 1);
        const float vr = sr[kl][nl], vi = si[kl][nl];
        const float c0 = ev ? vr : vi;
        const float c1 = ev ? -vi : vr;
        const size_t off2 = (size_t)(n0 * 2 + jl) * (K1 / 2) + (k0 + kl);
        __nv_bfloat162 v;
        v.x = __float2bfloat16_rn(c0);
        v.y = __float2bfloat16_rn(c1);
        ((__nv_bfloat162*)g_Bh)[off2] = v;
    }
}

// ---------------- GEMM: D = A @ B^T (bf16), split-K ----------------
// Grid (ARR/MT=4, NPAD/NT=3, ZSPLIT=32) = 384 CTAs, 256 threads (8 warps, 2M x 4N).
// Stage tile: 128 rows x 128B = [A 64B | B 64B], XOR-swizzled 16B granules.
// 3-stage cp.async pipeline, one __syncthreads per stage, BK=32 (2 k-steps of 16).
__global__ __launch_bounds__(256, 2) void gemm_mma_kernel()
{
    __shared__ __align__(128) unsigned char sT[SBUF][STAGEB];   // 48 KB

    const int tid = threadIdx.x;
    const int wid = tid >> 5;
    const int lane = tid & 31;
    const int m0 = blockIdx.x * MT;
    const int n0 = blockIdx.y * NT;
    const int bz = blockIdx.z;
    const int kc0 = bz * KCHUNK;

    const u32 smbase = smem_u32(sT);

    // ---- cp.async addressing: row r = tid>>1, 16B column cc = tid&1
    // A granules 0..3 (p=0,1), B granules 4..7 (p=2,3)
    const int r = tid >> 1;
    const int cc = tid & 1;
    u32 doff[4];
    const __nv_bfloat16* srcp[4];
#pragma unroll
    for (int p = 0; p < 4; ++p) {
        const int g = p * 2 + cc;              // 0..7 across p
        doff[p] = (u32)(r * 128 + ((g ^ (r & 7)) << 4));
        if (p < 2)
            srcp[p] = g_Ah + (size_t)(m0 + r) * K1 + kc0 + g * 8;
        else
            srcp[p] = g_Bh + (size_t)(n0 + r) * K1 + kc0 + (g - 4) * 8;
    }

    const int wm = wid >> 2;          // 0..1 -> 64 rows of M
    const int wn = wid & 3;           // 0..3 -> 32 cols of N

    float D[4][4][4];
#pragma unroll
    for (int mi = 0; mi < 4; ++mi)
#pragma unroll
        for (int ni = 0; ni < 4; ++ni)
#pragma unroll
            for (int e = 0; e < 4; ++e) D[mi][ni][e] = 0.f;

    // ---- prologue: stages 0,1
#pragma unroll
    for (int st = 0; st < 2; ++st) {
        const u32 b = smbase + st * STAGEB;
#pragma unroll
        for (int p = 0; p < 4; ++p)
            CP_ASYNC16(b + doff[p], srcp[p] + st * BK);
        CP_COMMIT();
    }

#pragma unroll 1
    for (int s = 0; s < NSTAGE; ++s) {
        if (s + 1 < NSTAGE) { CP_WAIT1(); } else { CP_WAIT0(); }
        __syncthreads();     // stage s visible; buf (s+2)%3 free to overwrite

        if (s + 2 < NSTAGE) {
            const u32 b = smbase + ((s + 2) % SBUF) * STAGEB;
#pragma unroll
            for (int p = 0; p < 4; ++p)
                CP_ASYNC16(b + doff[p], srcp[p] + (s + 2) * BK);
            CP_COMMIT();
        }

        const u32 buf = smbase + (s % SBUF) * STAGEB;

        // B fragments: [t = k-step 0,1][nc = 16-col group 0,1], pairing (r0,r2)/(r1,r3)
        u32 Bf[2][2][4];
#pragma unroll
        for (int nc = 0; nc < 2; ++nc) {
            const int row = wn * 32 + nc * 16 + (lane & 7) + ((lane >> 3) & 1) * 8;
#pragma unroll
            for (int t = 0; t < 2; ++t) {
                const u32 g = (u32)((4 + t * 2 + (lane >> 4)) ^ (row & 7));
                LDSM_X4(Bf[t][nc], buf + row * 128 + (g << 4));
            }
        }

#pragma unroll
        for (int mi = 0; mi < 4; ++mi) {
            const int row = wm * 64 + mi * 16 + (lane & 15);
            u32 Af[2][4];
#pragma unroll
            for (int t = 0; t < 2; ++t) {
                const u32 g = (u32)((t * 2 + (lane >> 4)) ^ (row & 7));
                LDSM_X4(Af[t], buf + row * 128 + (g << 4));
            }
#pragma unroll
            for (int ni = 0; ni < 4; ++ni) {
#pragma unroll
                for (int t = 0; t < 2; ++t) {
                    const u32 b0 = Bf[t][ni >> 1][ni & 1];
                    const u32 b1 = Bf[t][ni >> 1][(ni & 1) + 2];
                    MMA16816(D[mi][ni], Af[t], b0, b1);
                }
            }
        }
    }

    // ---- epilogue: write split-K partial tile (disjoint per bz -> deterministic)
    float* __restrict__ out = g_Dp[bz];
    const int rbase = m0 + wm * 64 + (lane >> 2);
    const int cbase = n0 + wn * 32 + (lane & 3) * 2;
#pragma unroll
    for (int mi = 0; mi < 4; ++mi) {
#pragma unroll
        for (int ni = 0; ni < 4; ++ni) {
            const int row = rbase + mi * 16;
            const int col = cbase + ni * 8;
            float2 v0; v0.x = D[mi][ni][0]; v0.y = D[mi][ni][1];
            float2 v1; v1.x = D[mi][ni][2]; v1.y = D[mi][ni][3];
            *(float2*)(out + (size_t)row * NPAD + col) = v0;
            *(float2*)(out + (size_t)(row + 8) * NPAD + col) = v1;
        }
    }
}

// ---------------- reduce split-K partials ----------------
__global__ __launch_bounds__(256) void reduceD_kernel()
{
    const int i = blockIdx.x * 256 + threadIdx.x;
    float s = 0.f;
#pragma unroll 8
    for (int z = 0; z < ZSPLIT; ++z) s += g_Dp[z][i];
    g_Dfull[i] = s;
}

// ---------------- sweep: sout = w_n @ B, fused |.|^2 + diag gather ----------------
// CPB=8 codes/block, planar float2 w in 32KB smem (packed via pk2 in-loop).
__global__ __launch_bounds__(192) void sweep_kernel(
    const float* __restrict__ w_re, const float* __restrict__ w_im,
    const int* __restrict__ sweep_angle)
{
    __shared__ float2 sw[CPB * ARR];   // normalized (wr, wi), 32 KB
    __shared__ float redP[6], redD[6];

    const int tid = threadIdx.x;
    const int c0 = blockIdx.x * CPB;

    for (int idx = tid; idx < CPB * ARR; idx += 192) {
        const int ci = idx >> 9;
        const int a = idx & (ARR - 1);
        const float wr = w_re[(size_t)(c0 + ci) * ARR + a];
        const float wi = w_im[(size_t)(c0 + ci) * ARR + a];
        const float rn = rsqrtf(wr * wr + wi * wi);
        sw[idx] = make_float2(wr * rn, wi * rn);
    }
    __syncthreads();

    float sumP = 0.f, sumD = 0.f;
    const int n = tid;
    if (n < NANG) {
        const u64* __restrict__ Brow = (const u64*)g_Dfull;   // (re,im) pairs, row = NPAD/2 u64
        u64 acc[CPB];
#pragma unroll
        for (int ci = 0; ci < CPB; ++ci) acc[ci] = pk2(0.f, 0.f);

#pragma unroll 2
        for (int a = 0; a < ARR; ++a) {
            const u64 bp = Brow[(size_t)a * (NPAD / 2) + n];   // (br, bi) coalesced
            const float2 b2 = unpk2(bp);
            const u64 bq = pk2(-b2.y, b2.x);                   // (-bi, br)
#pragma unroll
            for (int ci = 0; ci < CPB; ++ci) {
                const float2 wv = sw[ci * ARR + a];
                acc[ci] = ffma2(pk2(wv.x, wv.x), bp, ffma2(pk2(wv.y, wv.y), bq, acc[ci]));
            }
        }
#pragma unroll
        for (int ci = 0; ci < CPB; ++ci) {
            const float2 s = unpk2(acc[ci]);
            const float p = s.x * s.x + s.y * s.y;
            sumP += p;
            if (sweep_angle[c0 + ci] + 90 == n) sumD += p;
        }
    }

#pragma unroll
    for (int off = 16; off > 0; off >>= 1) {
        sumP += __shfl_down_sync(0xffffffffu, sumP, off);
        sumD += __shfl_down_sync(0xffffffffu, sumD, off);
    }
    if ((tid & 31) == 0) { redP[tid >> 5] = sumP; redD[tid >> 5] = sumD; }
    __syncthreads();
    if (tid == 0) {
        float P = 0.f, Dd = 0.f;
#pragma unroll
        for (int i = 0; i < 6; ++i) { P += redP[i]; Dd += redD[i]; }
        g_P[blockIdx.x] = P;
        g_D[blockIdx.x] = Dd;
    }
}

// ---------------- finalize: out = K*S - (1+2K)*D, K = 0.1 ----------------
__global__ __launch_bounds__(SWEEP_BLOCKS) void finalize_kernel(float* __restrict__ out)
{
    __shared__ float rP[SWEEP_BLOCKS], rD[SWEEP_BLOCKS];
    const int t = threadIdx.x;
    rP[t] = g_P[t];
    rD[t] = g_D[t];
    __syncthreads();
#pragma unroll
    for (int s = SWEEP_BLOCKS / 2; s > 0; s >>= 1) {
        if (t < s) { rP[t] += rP[t + s]; rD[t] += rD[t + s]; }
        __syncthreads();
    }
    if (t == 0) out[0] = 0.1f * rP[0] - 1.2f * rD[0];
}

// ---------------- launch ----------------
extern "C" void kernel_launch(void* const* d_in, const int* in_sizes, int n_in,
                              void* d_out, int out_size)
{
    (void)in_sizes; (void)n_in; (void)out_size;
    const float* w_re  = (const float*)d_in[0];
    const float* w_im  = (const float*)d_in[1];
    const float* th_re = (const float*)d_in[2];
    const float* th_im = (const float*)d_in[3];
    const float* G_re  = (const float*)d_in[4];
    const float* G_im  = (const float*)d_in[5];
    const float* st_re = (const float*)d_in[6];
    const float* st_im = (const float*)d_in[7];
    const int* sweep   = (const int*)d_in[10];   // addw (d_in[8],[9]) unused: var term * 0.0

    convA_kernel<<<(ARR * LENS) / 256, 256>>>(G_re, G_im, th_re, th_im);
    convB_kernel<<<dim3(LENS / 32, NPAD / 64, 1), 256>>>(st_re, st_im);
    gemm_mma_kernel<<<dim3(ARR / MT, NPAD / NT, ZSPLIT), 256>>>();
    reduceD_kernel<<<(ARR * NPAD) / 256, 256>>>();
    sweep_kernel<<<SWEEP_BLOCKS, 192>>>(w_re, w_im, sweep);
    finalize_kernel<<<1, SWEEP_BLOCKS>>>((float*)d_out);
}